// round 1
// baseline (speedup 1.0000x reference)
#include <cuda_runtime.h>
#include <math.h>

#define B_  8
#define L_  8
#define C_  64
#define P_  1024      // 32*32 pixels
#define NH_ 128
#define MSP 8192      // L*P spatial keys
#define MCH 512       // L*C channel keys

// ---------------- scratch (static device memory; no allocations) -------------
__device__ float g_Opart[2][B_][P_][C_];   // 4 MB  unnormalized flash partials
__device__ float g_m[2][B_][P_];
__device__ float g_l[2][B_][P_];
__device__ float g_xs[B_][C_][P_];         // sp + query   (conv input, stem 0)
__device__ float g_xc[B_][C_][P_];         // ch + query   (conv input, stem 1)
__device__ float g_att[B_][C_][MCH];       // channel logits -> probs (in place)
__device__ float g_y1[2][B_][C_][P_];      // conv1 outputs
__device__ float g_stats[2][B_][2];        // mean, rstd per (stem, batch)

// =============================================================================
// 1) Flash spatial attention. grid (ksplit=2, qtile=8, batch=8), 256 threads.
//    TQ=128 queries, TK=128 keys per tile, 8x8 register tile per thread.
//    smem feature-major: Qs/Ks/Vs [64][132], Ps [128][132].
// =============================================================================
#define TQ 128
#define TK 128
#define STR 132
#define FLASH_SMEM ((3*64*STR + 128*STR) * 4)

__global__ __launch_bounds__(256, 1)
void flash_kernel(const float* __restrict__ q,
                  const float* __restrict__ keys,
                  const float* __restrict__ vals)
{
    extern __shared__ float sm[];
    float* Qs = sm;                 // [c][q]
    float* Ks = sm + 64 * STR;      // [c][k]
    float* Vs = sm + 2 * 64 * STR;  // [c][k]
    float* Ps = sm + 3 * 64 * STR;  // [k][q]

    const int ks = blockIdx.x;
    const int qt = blockIdx.y;
    const int b  = blockIdx.z;
    const int tid = threadIdx.x;
    const int ty = tid >> 4;        // 0..15  (query groups)
    const int tx = tid & 15;        // 0..15  (key / out-channel groups)

    // load Q tile: Qs[c][qq] = q[b][c][qt*128+qq]
    const float* qg = q + (size_t)b * C_ * P_ + qt * TQ;
    for (int i4 = tid; i4 < C_ * TQ / 4; i4 += 256) {
        int c  = i4 >> 5;
        int q4 = (i4 & 31) << 2;
        float4 v = *reinterpret_cast<const float4*>(qg + c * P_ + q4);
        *reinterpret_cast<float4*>(Qs + c * STR + q4) = v;
    }

    float o[8][4];
    float mi[8], li[8];
#pragma unroll
    for (int i = 0; i < 8; i++) {
        mi[i] = -1e30f; li[i] = 0.f;
#pragma unroll
        for (int j = 0; j < 4; j++) o[i][j] = 0.f;
    }

    for (int t = 0; t < 32; ++t) {
        const int kb = ks * 4096 + t * TK;
        const int l  = kb >> 10;
        const int p0 = kb & 1023;
        const float* kg = keys + ((size_t)(b * L_ + l) * C_) * P_ + p0;
        const float* vg = vals + ((size_t)(b * L_ + l) * C_) * P_ + p0;

        __syncthreads();   // previous PV done before overwriting Ks/Vs
        for (int i4 = tid; i4 < C_ * TK / 4; i4 += 256) {
            int c  = i4 >> 5;
            int k4 = (i4 & 31) << 2;
            *reinterpret_cast<float4*>(Ks + c * STR + k4) =
                *reinterpret_cast<const float4*>(kg + c * P_ + k4);
            *reinterpret_cast<float4*>(Vs + c * STR + k4) =
                *reinterpret_cast<const float4*>(vg + c * P_ + k4);
        }
        __syncthreads();

        // --- S = Q^T K  (S[q][k], 8x8 per thread) ---
        float s[8][8];
#pragma unroll
        for (int i = 0; i < 8; i++)
#pragma unroll
            for (int j = 0; j < 8; j++) s[i][j] = 0.f;

#pragma unroll 4
        for (int c = 0; c < 64; ++c) {
            float qv[8], kv[8];
#pragma unroll
            for (int i = 0; i < 8; i++) qv[i] = Qs[c * STR + ty + 16 * i];
#pragma unroll
            for (int j = 0; j < 8; j++) kv[j] = Ks[c * STR + tx + 16 * j];
#pragma unroll
            for (int i = 0; i < 8; i++)
#pragma unroll
                for (int j = 0; j < 8; j++)
                    s[i][j] = fmaf(qv[i], kv[j], s[i][j]);
        }

        // --- online softmax (row reduce across the 16 tx lanes) ---
#pragma unroll
        for (int i = 0; i < 8; i++) {
            float tm = s[i][0];
#pragma unroll
            for (int j = 1; j < 8; j++) tm = fmaxf(tm, s[i][j]);
#pragma unroll
            for (int off = 1; off < 16; off <<= 1)
                tm = fmaxf(tm, __shfl_xor_sync(0xffffffffu, tm, off));
            float mn = fmaxf(mi[i], tm);
            float al = __expf(mi[i] - mn);
            mi[i] = mn;
            float rs = 0.f;
#pragma unroll
            for (int j = 0; j < 8; j++) {
                float pv = __expf(s[i][j] - mn);
                s[i][j] = pv;
                rs += pv;
            }
#pragma unroll
            for (int off = 1; off < 16; off <<= 1)
                rs += __shfl_xor_sync(0xffffffffu, rs, off);
            li[i] = li[i] * al + rs;
#pragma unroll
            for (int jc = 0; jc < 4; jc++) o[i][jc] *= al;
            // write P (k-major): Ps[k][q]
#pragma unroll
            for (int j = 0; j < 8; j++)
                Ps[(tx + 16 * j) * STR + ty + 16 * i] = s[i][j];
        }
        __syncthreads();

        // --- O += P V  (O[q][c], 8x4 per thread) ---
#pragma unroll 2
        for (int k = 0; k < TK; ++k) {
            float pv[8], vv[4];
#pragma unroll
            for (int i = 0; i < 8; i++) pv[i] = Ps[k * STR + ty + 16 * i];
#pragma unroll
            for (int jc = 0; jc < 4; jc++) vv[jc] = Vs[(tx + 16 * jc) * STR + k];
#pragma unroll
            for (int i = 0; i < 8; i++)
#pragma unroll
                for (int jc = 0; jc < 4; jc++)
                    o[i][jc] = fmaf(pv[i], vv[jc], o[i][jc]);
        }
    }

    // epilogue: write unnormalized partials + stats
#pragma unroll
    for (int i = 0; i < 8; i++) {
        int qrow = qt * TQ + ty + 16 * i;
        if (tx == 0) {
            g_m[ks][b][qrow] = mi[i];
            g_l[ks][b][qrow] = li[i];
        }
#pragma unroll
        for (int jc = 0; jc < 4; jc++)
            g_Opart[ks][b][qrow][tx + 16 * jc] = o[i][jc];
    }
}

// =============================================================================
// 2) Merge the two key-splits, add query residual, write [c][p] layout.
//    grid (qtile=8, batch=8), 256 threads.
// =============================================================================
__global__ void combine_kernel(const float* __restrict__ q)
{
    const int qt = blockIdx.x;
    const int b  = blockIdx.y;
    const int tid = threadIdx.x;
    for (int i = tid; i < 128 * 64; i += 256) {
        int qq = qt * 128 + (i >> 6);
        int c  = i & 63;
        float m0 = g_m[0][b][qq], m1 = g_m[1][b][qq];
        float M  = fmaxf(m0, m1);
        float e0 = __expf(m0 - M), e1 = __expf(m1 - M);
        float denom = g_l[0][b][qq] * e0 + g_l[1][b][qq] * e1;
        float val = (g_Opart[0][b][qq][c] * e0 + g_Opart[1][b][qq][c] * e1) / denom;
        g_xs[b][c][qq] = val + q[((size_t)b * C_ + c) * P_ + qq];
    }
}

// =============================================================================
// 3) Channel attention logits: logits[b][c][m] = sum_n q[b][c][n]*k[b][m][n]
//    grid (mtile=4, batch=8), 256 threads. Tiled over n (8 chunks of 128).
// =============================================================================
#define CAL_SMEM ((64*STR + 128*STR) * 4)

__global__ __launch_bounds__(256, 1)
void ca_logits_kernel(const float* __restrict__ q,
                      const float* __restrict__ keys)
{
    extern __shared__ float sm[];
    float* Qs = sm;              // [c 64][n 128] stride STR
    float* Ks = sm + 64 * STR;   // [m 128][n 128] stride STR

    const int mt = blockIdx.x;
    const int b  = blockIdx.y;
    const int tid = threadIdx.x;
    const int ty = tid >> 4;
    const int tx = tid & 15;

    float acc[4][8];
#pragma unroll
    for (int i = 0; i < 4; i++)
#pragma unroll
        for (int j = 0; j < 8; j++) acc[i][j] = 0.f;

    const float* qb = q + (size_t)b * C_ * P_;
    const float* kb = keys + (size_t)b * MCH * P_;

    for (int nt = 0; nt < 8; ++nt) {
        __syncthreads();
        for (int i4 = tid; i4 < 2048; i4 += 256) {          // Qs: 64x128
            int c  = i4 >> 5;
            int n4 = (i4 & 31) << 2;
            *reinterpret_cast<float4*>(Qs + c * STR + n4) =
                *reinterpret_cast<const float4*>(qb + c * P_ + nt * 128 + n4);
        }
        for (int i4 = tid; i4 < 4096; i4 += 256) {          // Ks: 128x128
            int mm = i4 >> 5;
            int n4 = (i4 & 31) << 2;
            *reinterpret_cast<float4*>(Ks + mm * STR + n4) =
                *reinterpret_cast<const float4*>(kb + (size_t)(mt * 128 + mm) * P_ + nt * 128 + n4);
        }
        __syncthreads();
#pragma unroll 4
        for (int n = 0; n < 128; ++n) {
            float qv[4], kv[8];
#pragma unroll
            for (int i = 0; i < 4; i++) qv[i] = Qs[(ty + 16 * i) * STR + n];
#pragma unroll
            for (int j = 0; j < 8; j++) kv[j] = Ks[(tx + 16 * j) * STR + n];
#pragma unroll
            for (int i = 0; i < 4; i++)
#pragma unroll
                for (int j = 0; j < 8; j++)
                    acc[i][j] = fmaf(qv[i], kv[j], acc[i][j]);
        }
    }
#pragma unroll
    for (int i = 0; i < 4; i++)
#pragma unroll
        for (int j = 0; j < 8; j++)
            g_att[b][ty + 16 * i][mt * 128 + tx + 16 * j] = acc[i][j];
}

// =============================================================================
// 4) Row softmax over 512 channel logits. grid (c=64, b=8), 128 threads.
// =============================================================================
__global__ void ca_softmax_kernel()
{
    const int c = blockIdx.x;
    const int b = blockIdx.y;
    const int tid = threadIdx.x;
    float* row = &g_att[b][c][0];
    float v[4];
#pragma unroll
    for (int r = 0; r < 4; r++) v[r] = row[tid + 128 * r];
    float mx = fmaxf(fmaxf(v[0], v[1]), fmaxf(v[2], v[3]));
#pragma unroll
    for (int off = 16; off > 0; off >>= 1)
        mx = fmaxf(mx, __shfl_xor_sync(0xffffffffu, mx, off));
    __shared__ float red[4], red2[4];
    if ((tid & 31) == 0) red[tid >> 5] = mx;
    __syncthreads();
    mx = fmaxf(fmaxf(red[0], red[1]), fmaxf(red[2], red[3]));
    float s = 0.f;
#pragma unroll
    for (int r = 0; r < 4; r++) { v[r] = __expf(v[r] - mx); s += v[r]; }
#pragma unroll
    for (int off = 16; off > 0; off >>= 1)
        s += __shfl_xor_sync(0xffffffffu, s, off);
    if ((tid & 31) == 0) red2[tid >> 5] = s;
    __syncthreads();
    s = red2[0] + red2[1] + red2[2] + red2[3];
    float inv = 1.f / s;
#pragma unroll
    for (int r = 0; r < 4; r++) row[tid + 128 * r] = v[r] * inv;
}

// =============================================================================
// 5) Channel attention apply: ch[b][c][n] = sum_m a[b][c][m] v[b][m][n] (+q).
//    grid (ntile=4, batch=8), 256 threads, 64 accumulators/thread.
// =============================================================================
__global__ __launch_bounds__(256, 1)
void ca_apply_kernel(const float* __restrict__ q,
                     const float* __restrict__ vals)
{
    __shared__ float As[128][68];  // [m][c]
    const int nt = blockIdx.x;
    const int b  = blockIdx.y;
    const int tid = threadIdx.x;
    const int n = nt * 256 + tid;

    float acc[64];
#pragma unroll
    for (int c = 0; c < 64; c++) acc[c] = 0.f;

    const float* vb = vals + (size_t)b * MCH * P_;

    for (int mc = 0; mc < 4; ++mc) {
        __syncthreads();
        for (int i = tid; i < 8192; i += 256) {
            int c  = i >> 7;
            int mm = i & 127;
            As[mm][c] = g_att[b][c][mc * 128 + mm];
        }
        __syncthreads();
#pragma unroll 2
        for (int mm = 0; mm < 128; ++mm) {
            float vv = vb[(size_t)(mc * 128 + mm) * P_ + n];
#pragma unroll
            for (int u = 0; u < 16; ++u) {
                float4 a4 = *reinterpret_cast<const float4*>(&As[mm][4 * u]);
                acc[4 * u + 0] = fmaf(a4.x, vv, acc[4 * u + 0]);
                acc[4 * u + 1] = fmaf(a4.y, vv, acc[4 * u + 1]);
                acc[4 * u + 2] = fmaf(a4.z, vv, acc[4 * u + 2]);
                acc[4 * u + 3] = fmaf(a4.w, vv, acc[4 * u + 3]);
            }
        }
    }
#pragma unroll
    for (int c = 0; c < 64; c++)
        g_xc[b][c][n] = acc[c] + q[((size_t)b * C_ + c) * P_ + n];
}

// =============================================================================
// 6) conv 5x5 (pad 2), 64->64. grid (cogroup=16, batch=8, stem=2), 256 threads.
//    4 out-channels per block, 4 pixels per thread.
// =============================================================================
#define COG 4
__global__ __launch_bounds__(256, 1)
void conv1_kernel(const float* __restrict__ s_w1, const float* __restrict__ s_b1,
                  const float* __restrict__ c_w1, const float* __restrict__ c_b1)
{
    __shared__ float Ws[COG * 64 * 25];  // 25.6 KB
    __shared__ float xs[36 * 36];        // padded plane

    const int cog = blockIdx.x;
    const int b   = blockIdx.y;
    const int st  = blockIdx.z;
    const int tid = threadIdx.x;
    const float* w    = st ? c_w1 : s_w1;
    const float* bias = st ? c_b1 : s_b1;
    const float* x    = st ? &g_xc[b][0][0] : &g_xs[b][0][0];
    const int co0 = cog * COG;

    for (int i = tid; i < COG * 64 * 25; i += 256)
        Ws[i] = w[co0 * 64 * 25 + i];

    float acc[COG][4];
#pragma unroll
    for (int u = 0; u < COG; u++) {
        float bv = bias[co0 + u];
#pragma unroll
        for (int r = 0; r < 4; r++) acc[u][r] = bv;
    }

    int pi[4], pj[4];
#pragma unroll
    for (int r = 0; r < 4; r++) {
        int p = tid + 256 * r;
        pi[r] = p >> 5;
        pj[r] = p & 31;
    }

    for (int ci = 0; ci < 64; ++ci) {
        __syncthreads();
        for (int i = tid; i < 1296; i += 256) {
            int rr = i / 36 - 2, cc = i % 36 - 2;
            xs[i] = (rr >= 0 && rr < 32 && cc >= 0 && cc < 32)
                        ? x[ci * P_ + rr * 32 + cc] : 0.f;
        }
        __syncthreads();
#pragma unroll
        for (int dy = 0; dy < 5; ++dy) {
#pragma unroll
            for (int dx = 0; dx < 5; ++dx) {
                float xv[4];
#pragma unroll
                for (int r = 0; r < 4; r++)
                    xv[r] = xs[(pi[r] + dy) * 36 + pj[r] + dx];
#pragma unroll
                for (int u = 0; u < COG; ++u) {
                    float wv = Ws[(u * 64 + ci) * 25 + dy * 5 + dx];
#pragma unroll
                    for (int r = 0; r < 4; r++)
                        acc[u][r] = fmaf(wv, xv[r], acc[u][r]);
                }
            }
        }
    }
#pragma unroll
    for (int u = 0; u < COG; ++u)
#pragma unroll
        for (int r = 0; r < 4; r++)
            g_y1[st][b][co0 + u][tid + 256 * r] = acc[u][r];
}

// =============================================================================
// 7) LayerNorm stats over [C,W,W] per (stem, batch). 16 blocks, 256 threads.
// =============================================================================
__global__ void ln_stats_kernel()
{
    const int id = blockIdx.x;
    const int st = id >> 3, b = id & 7;
    const float* y = &g_y1[st][b][0][0];
    const int tid = threadIdx.x;
    float s = 0.f, s2 = 0.f;
    for (int i = tid; i < C_ * P_; i += 256) {
        float v = y[i];
        s += v;
        s2 = fmaf(v, v, s2);
    }
#pragma unroll
    for (int off = 16; off > 0; off >>= 1) {
        s  += __shfl_xor_sync(0xffffffffu, s,  off);
        s2 += __shfl_xor_sync(0xffffffffu, s2, off);
    }
    __shared__ float rs[8], rs2[8];
    if ((tid & 31) == 0) { rs[tid >> 5] = s; rs2[tid >> 5] = s2; }
    __syncthreads();
    if (tid == 0) {
        float S = 0.f, S2 = 0.f;
        for (int wv = 0; wv < 8; wv++) { S += rs[wv]; S2 += rs2[wv]; }
        float inv = 1.f / (float)(C_ * P_);
        float mean = S * inv;
        float var  = S2 * inv - mean * mean;
        g_stats[st][b][0] = mean;
        g_stats[st][b][1] = rsqrtf(var + 1e-5f);
    }
}

// =============================================================================
// 8) LN apply + ReLU + 1x1 conv (64->128) + bias, write output.
//    grid (ptile=4, batch=8, stem=2), 256 threads, 128 accumulators/thread.
// =============================================================================
__global__ __launch_bounds__(256, 1)
void conv2_kernel(const float* __restrict__ s_lnw, const float* __restrict__ s_lnb,
                  const float* __restrict__ s_w2,  const float* __restrict__ s_b2,
                  const float* __restrict__ c_lnw, const float* __restrict__ c_lnb,
                  const float* __restrict__ c_w2,  const float* __restrict__ c_b2,
                  float* __restrict__ out)
{
    __shared__ float Ws[64 * 128];  // [c][nh], 32 KB
    const int pt = blockIdx.x;
    const int b  = blockIdx.y;
    const int st = blockIdx.z;
    const int tid = threadIdx.x;
    const float* lnw = st ? c_lnw : s_lnw;
    const float* lnb = st ? c_lnb : s_lnb;
    const float* w2  = st ? c_w2  : s_w2;
    const float* b2  = st ? c_b2  : s_b2;

    for (int i = tid; i < NH_ * C_; i += 256) {
        int nh = i >> 6, c = i & 63;
        Ws[c * NH_ + nh] = w2[i];
    }
    __syncthreads();

    const int p = pt * 256 + tid;
    const float mean = g_stats[st][b][0];
    const float rstd = g_stats[st][b][1];

    float acc[NH_];
#pragma unroll
    for (int nh = 0; nh < NH_; nh++) acc[nh] = 0.f;

    for (int c = 0; c < 64; ++c) {
        float yv = g_y1[st][b][c][p];
        float t = (yv - mean) * rstd;
        t = fmaf(t, lnw[c * P_ + p], lnb[c * P_ + p]);
        t = fmaxf(t, 0.f);
#pragma unroll
        for (int u = 0; u < 32; ++u) {
            float4 w4 = *reinterpret_cast<const float4*>(&Ws[c * NH_ + 4 * u]);
            acc[4 * u + 0] = fmaf(w4.x, t, acc[4 * u + 0]);
            acc[4 * u + 1] = fmaf(w4.y, t, acc[4 * u + 1]);
            acc[4 * u + 2] = fmaf(w4.z, t, acc[4 * u + 2]);
            acc[4 * u + 3] = fmaf(w4.w, t, acc[4 * u + 3]);
        }
    }
    float* ob = out + ((size_t)st * B_ + b) * NH_ * P_;
#pragma unroll
    for (int nh = 0; nh < NH_; nh++)
        ob[(size_t)nh * P_ + p] = acc[nh] + b2[nh];
}

// =============================================================================
// host launcher
// =============================================================================
extern "C" void kernel_launch(void* const* d_in, const int* in_sizes, int n_in,
                              void* d_out, int out_size)
{
    const float* q    = (const float*)d_in[0];
    const float* keys = (const float*)d_in[1];
    const float* vals = (const float*)d_in[2];
    const float* s_w1 = (const float*)d_in[3];
    const float* s_b1 = (const float*)d_in[4];
    const float* s_lnw = (const float*)d_in[5];
    const float* s_lnb = (const float*)d_in[6];
    const float* s_w2 = (const float*)d_in[7];
    const float* s_b2 = (const float*)d_in[8];
    const float* c_w1 = (const float*)d_in[9];
    const float* c_b1 = (const float*)d_in[10];
    const float* c_lnw = (const float*)d_in[11];
    const float* c_lnb = (const float*)d_in[12];
    const float* c_w2 = (const float*)d_in[13];
    const float* c_b2 = (const float*)d_in[14];
    float* out = (float*)d_out;

    cudaFuncSetAttribute(flash_kernel,
                         cudaFuncAttributeMaxDynamicSharedMemorySize, FLASH_SMEM);
    cudaFuncSetAttribute(ca_logits_kernel,
                         cudaFuncAttributeMaxDynamicSharedMemorySize, CAL_SMEM);

    flash_kernel<<<dim3(2, 8, 8), 256, FLASH_SMEM>>>(q, keys, vals);
    combine_kernel<<<dim3(8, 8), 256>>>(q);
    ca_logits_kernel<<<dim3(4, 8), 256, CAL_SMEM>>>(q, keys);
    ca_softmax_kernel<<<dim3(64, 8), 128>>>();
    ca_apply_kernel<<<dim3(4, 8), 256>>>(q, vals);
    conv1_kernel<<<dim3(16, 8, 2), 256>>>(s_w1, s_b1, c_w1, c_b1);
    ln_stats_kernel<<<16, 256>>>();
    conv2_kernel<<<dim3(4, 8, 2), 256>>>(s_lnw, s_lnb, s_w2, s_b2,
                                         c_lnw, c_lnb, c_w2, c_b2, out);
}